// round 1
// baseline (speedup 1.0000x reference)
#include <cuda_runtime.h>
#include <cuda_bf16.h>

// Problem constants (fixed by the dataset)
#define BATCH 512
#define TSTEPS 256
#define HID 512
#define G4 2048          // 4*HID
#define DEC_STEPS 42

// GEMM tile config
#define TM 64            // batch rows per CTA
#define TN 32            // columns per gate per CTA (CTA covers 4 gate quadrants)
#define TK 32            // k tile
#define NKT (HID / TK)   // 16 k-tiles

// Scratch (allocation-free rule: __device__ globals)
__device__ float g_h0[BATCH * HID];
__device__ float g_h1[BATCH * HID];
__device__ float g_c [BATCH * HID];
__device__ float g_G0[BATCH * G4];

__device__ __forceinline__ float sigm(float v) { return 1.0f / (1.0f + expf(-v)); }

// ---------------------------------------------------------------------------
// zero h0 and c at the start of every launch (deterministic)
// ---------------------------------------------------------------------------
__global__ void zero_kernel(float* __restrict__ a, float* __restrict__ b, int n) {
    int i = blockIdx.x * blockDim.x + threadIdx.x;
    if (i < n) { a[i] = 0.0f; b[i] = 0.0f; }
}

// ---------------------------------------------------------------------------
// One LSTM timestep:
//   gates[b, q*512+j] = sum_k hin[b,k] * Whh[q*512+j, k]  (+ bias + x-term)
// CTA tile: 64 batch rows x 32 cols, all 4 gate quadrants -> fused c/h update.
// If gatesOut != nullptr: store raw gates+bias (no x term, no state update)
// — used once to build the decoder's fixed G0.
// Block: 256 threads = 8(ty) x 32(tx). Thread: 8 rows x 1 col x 4 gates.
// ---------------------------------------------------------------------------
__global__ __launch_bounds__(256, 2)
void lstm_step_kernel(const float* __restrict__ hin,
                      float* __restrict__ hout,
                      float* __restrict__ c,
                      const float* __restrict__ Whh,   // [2048, 512] row-major
                      const float* __restrict__ b_ih,  // [2048]
                      const float* __restrict__ b_hh,  // [2048]
                      const float* __restrict__ Wih,   // [2048] (IN==1)
                      const float* __restrict__ x,     // [B, T] (IN==1), or null
                      int t,
                      float* __restrict__ gatesOut)    // null => LSTM update
{
    // k-transposed smem: sA[kk][row], sW[q][kk][col]
    __shared__ __align__(16) float sA[TK * 68];            // pad 68: float4-aligned, STS 4-way max
    __shared__ float sW[4 * TK * 33];                      // pad 33: conflict-free

    const int tid = threadIdx.x;
    const int tx = tid & 31;          // col within gate tile
    const int ty = tid >> 5;          // row-group (8 rows each)
    const int n0 = blockIdx.x * TN;   // gate-column tile base (0..511)
    const int m0 = blockIdx.y * TM;   // batch-row tile base

    float acc[4][8];
#pragma unroll
    for (int q = 0; q < 4; ++q)
#pragma unroll
        for (int im = 0; im < 8; ++im) acc[q][im] = 0.0f;

    for (int kt = 0; kt < NKT; ++kt) {
        const int k0 = kt * TK;
        __syncthreads();
        // load h tile: 64x32 floats, coalesced in k
#pragma unroll
        for (int i = 0; i < 8; ++i) {
            int idx = tid + i * 256;          // 0..2047
            int kk = idx & 31;
            int r  = idx >> 5;                // 0..63
            sA[kk * 68 + r] = hin[(m0 + r) * HID + k0 + kk];
        }
        // load W tiles: 4 x 32x32 floats, coalesced in k
#pragma unroll
        for (int i = 0; i < 16; ++i) {
            int idx = tid + i * 256;          // 0..4095
            int kk  = idx & 31;
            int rem = idx >> 5;               // 0..127
            int nn  = rem & 31;
            int q   = rem >> 5;
            sW[q * (TK * 33) + kk * 33 + nn] =
                Whh[(q * HID + n0 + nn) * HID + k0 + kk];
        }
        __syncthreads();

#pragma unroll
        for (int kk = 0; kk < TK; ++kk) {
            const float4* pa = reinterpret_cast<const float4*>(&sA[kk * 68 + ty * 8]);
            float4 a0 = pa[0];
            float4 a1 = pa[1];
            float av[8] = {a0.x, a0.y, a0.z, a0.w, a1.x, a1.y, a1.z, a1.w};
            float bq[4];
#pragma unroll
            for (int q = 0; q < 4; ++q) bq[q] = sW[q * (TK * 33) + kk * 33 + tx];
#pragma unroll
            for (int q = 0; q < 4; ++q)
#pragma unroll
                for (int im = 0; im < 8; ++im)
                    acc[q][im] = fmaf(av[im], bq[q], acc[q][im]);
        }
    }

    // epilogue
    const int jj = n0 + tx;
    float bias[4], wv[4];
#pragma unroll
    for (int q = 0; q < 4; ++q) {
        bias[q] = b_ih[q * HID + jj] + b_hh[q * HID + jj];
        wv[q]   = Wih[q * HID + jj];
    }

    if (gatesOut != nullptr) {
#pragma unroll
        for (int im = 0; im < 8; ++im) {
            int row = m0 + ty * 8 + im;
#pragma unroll
            for (int q = 0; q < 4; ++q)
                gatesOut[row * G4 + q * HID + jj] = acc[q][im] + bias[q];
        }
    } else {
#pragma unroll
        for (int im = 0; im < 8; ++im) {
            int row = m0 + ty * 8 + im;
            float xv = x[row * TSTEPS + t];
            float gi = acc[0][im] + bias[0] + xv * wv[0];
            float gf = acc[1][im] + bias[1] + xv * wv[1];
            float gg = acc[2][im] + bias[2] + xv * wv[2];
            float go = acc[3][im] + bias[3] + xv * wv[3];
            int idx = row * HID + jj;
            float cn = sigm(gf) * c[idx] + sigm(gi) * tanhf(gg);
            c[idx] = cn;
            hout[idx] = sigm(go) * tanhf(cn);
        }
    }
}

// ---------------------------------------------------------------------------
// Decoder: hidden/cell fixed; gates = G0 + out*wih (rank-1). One CTA per batch
// row, 42 steps in-kernel. 256 threads, each owns columns t and t+256.
// ---------------------------------------------------------------------------
__global__ __launch_bounds__(256)
void decode_kernel(const float* __restrict__ hidden,
                   const float* __restrict__ cell,
                   const float* __restrict__ G0,
                   const float* __restrict__ Wih,
                   const float* __restrict__ Wout,   // [512]
                   const float* __restrict__ bout,   // [1]
                   float* __restrict__ out)          // [B, 42]
{
    const int b = blockIdx.x;
    const int t = threadIdx.x;

    __shared__ float sh[HID];
    __shared__ float red[9];

    float g0[2][4], wv[2][4], cc[2], wo[2];
#pragma unroll
    for (int s = 0; s < 2; ++s) {
        int jj = t + s * 256;
#pragma unroll
        for (int q = 0; q < 4; ++q) {
            g0[s][q] = G0[b * G4 + q * HID + jj];
            wv[s][q] = Wih[q * HID + jj];
        }
        cc[s] = cell[b * HID + jj];
        wo[s] = Wout[jj];
        sh[jj] = hidden[b * HID + jj];
    }
    const float bo = bout[0];
    __syncthreads();

    for (int step = 0; step < DEC_STEPS; ++step) {
        // out = h . Wout + b_out
        float p = sh[t] * wo[0] + sh[t + 256] * wo[1];
#pragma unroll
        for (int o = 16; o > 0; o >>= 1)
            p += __shfl_down_sync(0xffffffffu, p, o);
        if ((t & 31) == 0) red[t >> 5] = p;
        __syncthreads();
        if (t < 8) {
            float v = red[t];
            v += __shfl_down_sync(0x000000ffu, v, 4);
            v += __shfl_down_sync(0x000000ffu, v, 2);
            v += __shfl_down_sync(0x000000ffu, v, 1);
            if (t == 0) red[8] = v + bo;
        }
        __syncthreads();
        const float ov = red[8];
        if (t == 0) out[b * DEC_STEPS + step] = ov;

        float hn[2];
#pragma unroll
        for (int s = 0; s < 2; ++s) {
            float gi = g0[s][0] + ov * wv[s][0];
            float gf = g0[s][1] + ov * wv[s][1];
            float gg = g0[s][2] + ov * wv[s][2];
            float go = g0[s][3] + ov * wv[s][3];
            float cn = sigm(gf) * cc[s] + sigm(gi) * tanhf(gg);
            hn[s] = sigm(go) * tanhf(cn);
        }
        __syncthreads();           // everyone done reading sh
        sh[t]       = hn[0];
        sh[t + 256] = hn[1];
        __syncthreads();
    }
}

// ---------------------------------------------------------------------------
extern "C" void kernel_launch(void* const* d_in, const int* in_sizes, int n_in,
                              void* d_out, int out_size)
{
    const float* x     = (const float*)d_in[0];  // [B, T, 1]
    const float* W_ih  = (const float*)d_in[1];  // [2048, 1]
    const float* W_hh  = (const float*)d_in[2];  // [2048, 512]
    const float* b_ih  = (const float*)d_in[3];  // [2048]
    const float* b_hh  = (const float*)d_in[4];  // [2048]
    const float* W_out = (const float*)d_in[5];  // [1, 512]
    const float* b_out = (const float*)d_in[6];  // [1]
    float* out = (float*)d_out;                  // [B, 42, 1]

    float *h0, *h1, *c, *G0;
    cudaGetSymbolAddress((void**)&h0, g_h0);
    cudaGetSymbolAddress((void**)&h1, g_h1);
    cudaGetSymbolAddress((void**)&c,  g_c);
    cudaGetSymbolAddress((void**)&G0, g_G0);

    // zero initial state every call (deterministic)
    {
        int n = BATCH * HID;
        zero_kernel<<<(n + 255) / 256, 256>>>(h0, c, n);
    }

    dim3 grid(HID / TN, BATCH / TM);   // (16, 8) = 128 CTAs
    dim3 block(256);

    // encoder: 256 sequential steps, ping-pong h buffers
    for (int t = 0; t < TSTEPS; ++t) {
        const float* hin = (t & 1) ? h1 : h0;
        float* hout      = (t & 1) ? h0 : h1;
        lstm_step_kernel<<<grid, block>>>(hin, hout, c, W_hh, b_ih, b_hh,
                                          W_ih, x, t, nullptr);
    }
    // after t=255 (odd): final hidden is in h0, final cell in c

    // fixed decoder base gates: G0 = hidden @ W_hh^T + (b_ih + b_hh)
    lstm_step_kernel<<<grid, block>>>(h0, h1, c, W_hh, b_ih, b_hh,
                                      W_ih, nullptr, 0, G0);

    // autoregressive decode (batch-parallel, 42 steps in-kernel)
    decode_kernel<<<BATCH, 256>>>(h0, c, G0, W_ih, W_out, b_out, out);
}

// round 3
// speedup vs baseline: 1.7294x; 1.7294x over previous
#include <cuda_runtime.h>
#include <cuda_bf16.h>
#include <cstdint>
#include <cstddef>

// Problem constants
#define BATCH 512
#define TSTEPS 256
#define HID 512
#define G4 2048
#define DEC_STEPS 42

// MMA step config
#define TM 64                 // batch rows per CTA
#define TNR 128               // reordered gate cols per CTA (= 32 logical x 4 gates)
#define KC 32                 // k chunk
#define NKC (HID / KC)        // 16 chunks
#define PA 40                 // smem pitch (elems) for A tiles (32 + 8 pad)
#define PB 40
#define ABYTES (TM * PA * 2)          // 5120
#define BBYTES (TNR * PB * 2)         // 10240
#define STAGE (2 * ABYTES + 2 * BBYTES)   // 30720 (Ahi,Alo,Bhi,Blo)
#define SMEM_TOTAL (2 * STAGE)            // 61440

// ------------------------- device scratch (no allocs) ----------------------
__device__ __align__(128) __nv_bfloat16 g_whi[G4 * HID];
__device__ __align__(128) __nv_bfloat16 g_wlo[G4 * HID];
__device__ __align__(128) __nv_bfloat16 g_hhi0[BATCH * HID];
__device__ __align__(128) __nv_bfloat16 g_hlo0[BATCH * HID];
__device__ __align__(128) __nv_bfloat16 g_hhi1[BATCH * HID];
__device__ __align__(128) __nv_bfloat16 g_hlo1[BATCH * HID];
__device__ float g_hf[BATCH * HID];
__device__ float g_c [BATCH * HID];
__device__ float g_G0[BATCH * G4];
__device__ float g_br[G4];
__device__ float g_wihr[G4];

// ------------------------------ helpers ------------------------------------
__device__ __forceinline__ uint32_t smem_u32(const void* p) {
    uint32_t a;
    asm("{ .reg .u64 t; cvta.to.shared.u64 t, %1; cvt.u32.u64 %0, t; }" : "=r"(a) : "l"(p));
    return a;
}
__device__ __forceinline__ void cpasync16(uint32_t s, const void* g) {
    asm volatile("cp.async.cg.shared.global [%0], [%1], 16;" :: "r"(s), "l"(g));
}
__device__ __forceinline__ void cpasync_commit() {
    asm volatile("cp.async.commit_group;" ::: "memory");
}
template <int N> __device__ __forceinline__ void cpasync_wait() {
    asm volatile("cp.async.wait_group %0;" :: "n"(N) : "memory");
}
__device__ __forceinline__ void ldsm_x4(uint32_t* r, uint32_t addr) {
    asm volatile("ldmatrix.sync.aligned.m8n8.x4.shared.b16 {%0,%1,%2,%3}, [%4];"
                 : "=r"(r[0]), "=r"(r[1]), "=r"(r[2]), "=r"(r[3]) : "r"(addr));
}
__device__ __forceinline__ void mma16816(float* c, const uint32_t* a, uint32_t b0, uint32_t b1) {
    asm volatile(
        "mma.sync.aligned.m16n8k16.row.col.f32.bf16.bf16.f32 "
        "{%0,%1,%2,%3}, {%4,%5,%6,%7}, {%8,%9}, {%0,%1,%2,%3};"
        : "+f"(c[0]), "+f"(c[1]), "+f"(c[2]), "+f"(c[3])
        : "r"(a[0]), "r"(a[1]), "r"(a[2]), "r"(a[3]), "r"(b0), "r"(b1));
}
__device__ __forceinline__ float sigm(float v) { return 1.0f / (1.0f + expf(-v)); }

// -------------------------- init / prep kernels -----------------------------
__global__ void init_state(uint32_t* hhi, uint32_t* hlo, float* c) {
    int i = blockIdx.x * 256 + threadIdx.x;
    if (i < BATCH * HID / 2) { hhi[i] = 0u; hlo[i] = 0u; }
    if (i < BATCH * HID) c[i] = 0.0f;
}

// Split W_hh into bf16 hi/lo with gate-interleaved row reorder:
//   old row r = q*512 + jn*32 + s  ->  new row = jn*128 + q*32 + s
__global__ void wprep(const float* __restrict__ Whh,
                      const float* __restrict__ b_ih, const float* __restrict__ b_hh,
                      const float* __restrict__ Wih,
                      __nv_bfloat16* __restrict__ whi, __nv_bfloat16* __restrict__ wlo,
                      float* __restrict__ br, float* __restrict__ wihr)
{
    int i = blockIdx.x * 256 + threadIdx.x;
    if (i >= G4 * HID) return;
    int old_r = i / HID;
    int k = i - old_r * HID;
    int q = old_r >> 9;
    int rem = old_r & 511;
    int jn = rem >> 5;
    int s = rem & 31;
    int new_r = jn * 128 + q * 32 + s;
    float w = Whh[i];
    __nv_bfloat16 hi = __float2bfloat16(w);
    whi[new_r * HID + k] = hi;
    wlo[new_r * HID + k] = __float2bfloat16(w - __bfloat162float(hi));
    if (k == 0) {
        br[new_r] = b_ih[old_r] + b_hh[old_r];
        wihr[new_r] = Wih[old_r];
    }
}

// ----------------------------- tensor LSTM step -----------------------------
__global__ __launch_bounds__(128, 1)
void lstm_mma_step(const __nv_bfloat16* __restrict__ ahi, const __nv_bfloat16* __restrict__ alo,
                   const __nv_bfloat16* __restrict__ whi, const __nv_bfloat16* __restrict__ wlo,
                   const float* __restrict__ br, const float* __restrict__ wihr,
                   const float* __restrict__ x, int t,
                   float* __restrict__ c,
                   __nv_bfloat16* __restrict__ hout_hi, __nv_bfloat16* __restrict__ hout_lo,
                   float* __restrict__ hf,     // non-null: also store fp32 h
                   float* __restrict__ G0)     // non-null: G0 mode (gates+bias only)
{
    extern __shared__ __align__(16) char smem[];
    const uint32_t sb = smem_u32(smem);
    const int tid = threadIdx.x;
    const int w = tid >> 5;
    const int l = tid & 31;
    const int jn = blockIdx.x;            // 0..15
    const int m0 = blockIdx.y * TM;
    const int n0 = jn * TNR;              // reordered W row base

    // --------------- cp.async tile loaders (row pitch 80B, 16B pad) ---------
    auto loadA = [&](uint32_t dst, const __nv_bfloat16* gsrc) {
#pragma unroll
        for (int it = 0; it < 2; ++it) {
            int slot = tid + it * 128;        // 0..255
            int r = slot >> 2;
            int cseg = slot & 3;
            cpasync16(dst + (uint32_t)(r * (PA * 2) + cseg * 16),
                      (const char*)gsrc + (size_t)r * (HID * 2) + cseg * 16);
        }
    };
    auto loadB = [&](uint32_t dst, const __nv_bfloat16* gsrc) {
#pragma unroll
        for (int it = 0; it < 4; ++it) {
            int slot = tid + it * 128;        // 0..511
            int r = slot >> 2;
            int cseg = slot & 3;
            cpasync16(dst + (uint32_t)(r * (PB * 2) + cseg * 16),
                      (const char*)gsrc + (size_t)r * (HID * 2) + cseg * 16);
        }
    };
    auto load_chunk = [&](int stage, int kc) {
        uint32_t st = sb + stage * STAGE;
        int k0 = kc * KC;
        loadA(st,                          ahi + (size_t)m0 * HID + k0);
        loadA(st + ABYTES,                 alo + (size_t)m0 * HID + k0);
        loadB(st + 2 * ABYTES,            whi + (size_t)n0 * HID + k0);
        loadB(st + 2 * ABYTES + BBYTES,   wlo + (size_t)n0 * HID + k0);
        cpasync_commit();
    };

    // per-lane ldmatrix byte offsets
    const uint32_t aoff = (uint32_t)((l & 15) * (PA * 2) + (l >> 4) * 16);
    const uint32_t boff = (uint32_t)(((l & 7) + ((l >> 4) << 3)) * (PB * 2) + ((l >> 3) & 1) * 16);

    float acc[4][4][4];
#pragma unroll
    for (int mt = 0; mt < 4; ++mt)
#pragma unroll
        for (int nt = 0; nt < 4; ++nt)
#pragma unroll
            for (int v = 0; v < 4; ++v) acc[mt][nt][v] = 0.0f;

    load_chunk(0, 0);

#pragma unroll 1
    for (int kc = 0; kc < NKC; ++kc) {
        if (kc < NKC - 1) {
            load_chunk((kc + 1) & 1, kc + 1);
            cpasync_wait<1>();
        } else {
            cpasync_wait<0>();
        }
        __syncthreads();

        const uint32_t st = sb + (kc & 1) * STAGE;
        const uint32_t stA = st;
        const uint32_t stB = st + 2 * ABYTES;
#pragma unroll
        for (int ks = 0; ks < 2; ++ks) {
            const uint32_t ka = (uint32_t)(ks * 32);   // 16 bf16 = 32B
            uint32_t ah[4][4], al[4][4];
#pragma unroll
            for (int mt = 0; mt < 4; ++mt) {
                ldsm_x4(ah[mt], stA + (uint32_t)(mt * 16 * (PA * 2)) + ka + aoff);
                ldsm_x4(al[mt], stA + ABYTES + (uint32_t)(mt * 16 * (PA * 2)) + ka + aoff);
            }
            uint32_t bh[2][4], bl[2][4];
#pragma unroll
            for (int bt = 0; bt < 2; ++bt) {
                uint32_t nb = (uint32_t)((w * 32 + bt * 16) * (PB * 2));
                ldsm_x4(bh[bt], stB + nb + ka + boff);
                ldsm_x4(bl[bt], stB + BBYTES + nb + ka + boff);
            }
#pragma unroll
            for (int mt = 0; mt < 4; ++mt)
#pragma unroll
                for (int nt = 0; nt < 4; ++nt) {
                    uint32_t h0 = bh[nt >> 1][(nt & 1) * 2], h1 = bh[nt >> 1][(nt & 1) * 2 + 1];
                    uint32_t l0 = bl[nt >> 1][(nt & 1) * 2], l1 = bl[nt >> 1][(nt & 1) * 2 + 1];
                    mma16816(acc[mt][nt], ah[mt], h0, h1);
                    mma16816(acc[mt][nt], ah[mt], l0, l1);
                    mma16816(acc[mt][nt], al[mt], h0, h1);
                }
        }
        __syncthreads();
    }

    // ------------------------------- epilogue --------------------------------
    // dump accumulators to smem as [64][132] fp32 (cols = q*32+s)
    float* sg = reinterpret_cast<float*>(smem);
#pragma unroll
    for (int mt = 0; mt < 4; ++mt)
#pragma unroll
        for (int nt = 0; nt < 4; ++nt) {
            int r0 = mt * 16 + (l >> 2);
            int cb = w * 32 + nt * 8 + (l & 3) * 2;
            *reinterpret_cast<float2*>(&sg[r0 * 132 + cb]) =
                make_float2(acc[mt][nt][0], acc[mt][nt][1]);
            *reinterpret_cast<float2*>(&sg[(r0 + 8) * 132 + cb]) =
                make_float2(acc[mt][nt][2], acc[mt][nt][3]);
        }
    __syncthreads();

    const int srow = tid >> 1;
    const int row = m0 + srow;
    const float xv = (G0 == nullptr) ? x[row * TSTEPS + t] : 0.0f;

#pragma unroll
    for (int i = 0; i < 16; ++i) {
        int s = (tid & 1) * 16 + i;
        float d0 = sg[srow * 132 + 0 * 32 + s];
        float d1 = sg[srow * 132 + 1 * 32 + s];
        float d2 = sg[srow * 132 + 2 * 32 + s];
        float d3 = sg[srow * 132 + 3 * 32 + s];
        float b0 = br[n0 + 0 * 32 + s];
        float b1 = br[n0 + 1 * 32 + s];
        float b2 = br[n0 + 2 * 32 + s];
        float b3 = br[n0 + 3 * 32 + s];
        int col = jn * 32 + s;
        if (G0 != nullptr) {
            size_t base = (size_t)row * G4;
            G0[base + 0 * HID + col] = d0 + b0;
            G0[base + 1 * HID + col] = d1 + b1;
            G0[base + 2 * HID + col] = d2 + b2;
            G0[base + 3 * HID + col] = d3 + b3;
        } else {
            float gi = d0 + b0 + xv * wihr[n0 + 0 * 32 + s];
            float gf = d1 + b1 + xv * wihr[n0 + 1 * 32 + s];
            float gg = d2 + b2 + xv * wihr[n0 + 2 * 32 + s];
            float go = d3 + b3 + xv * wihr[n0 + 3 * 32 + s];
            int idx = row * HID + col;
            float cn = sigm(gf) * c[idx] + sigm(gi) * tanhf(gg);
            c[idx] = cn;
            float hv = sigm(go) * tanhf(cn);
            __nv_bfloat16 hi = __float2bfloat16(hv);
            hout_hi[idx] = hi;
            hout_lo[idx] = __float2bfloat16(hv - __bfloat162float(hi));
            if (hf != nullptr) hf[idx] = hv;
        }
    }
}

// ------------------------------- decoder ------------------------------------
__global__ __launch_bounds__(256)
void decode_kernel(const float* __restrict__ hidden,
                   const float* __restrict__ cell,
                   const float* __restrict__ G0,
                   const float* __restrict__ Wih,
                   const float* __restrict__ Wout,
                   const float* __restrict__ bout,
                   float* __restrict__ out)
{
    const int b = blockIdx.x;
    const int t = threadIdx.x;

    __shared__ float sh[HID];
    __shared__ float red[9];

    float g0[2][4], wv[2][4], cc[2], wo[2];
#pragma unroll
    for (int s = 0; s < 2; ++s) {
        int jj = t + s * 256;
#pragma unroll
        for (int q = 0; q < 4; ++q) {
            g0[s][q] = G0[b * G4 + q * HID + jj];
            wv[s][q] = Wih[q * HID + jj];
        }
        cc[s] = cell[b * HID + jj];
        wo[s] = Wout[jj];
        sh[jj] = hidden[b * HID + jj];
    }
    const float bo = bout[0];
    __syncthreads();

    for (int step = 0; step < DEC_STEPS; ++step) {
        float p = sh[t] * wo[0] + sh[t + 256] * wo[1];
#pragma unroll
        for (int o = 16; o > 0; o >>= 1)
            p += __shfl_down_sync(0xffffffffu, p, o);
        if ((t & 31) == 0) red[t >> 5] = p;
        __syncthreads();
        if (t < 8) {
            float v = red[t];
            v += __shfl_down_sync(0x000000ffu, v, 4);
            v += __shfl_down_sync(0x000000ffu, v, 2);
            v += __shfl_down_sync(0x000000ffu, v, 1);
            if (t == 0) red[8] = v + bo;
        }
        __syncthreads();
        const float ov = red[8];
        if (t == 0) out[b * DEC_STEPS + step] = ov;

        float hn[2];
#pragma unroll
        for (int s = 0; s < 2; ++s) {
            float gi = g0[s][0] + ov * wv[s][0];
            float gf = g0[s][1] + ov * wv[s][1];
            float gg = g0[s][2] + ov * wv[s][2];
            float go = g0[s][3] + ov * wv[s][3];
            float cn = sigm(gf) * cc[s] + sigm(gi) * tanhf(gg);
            hn[s] = sigm(go) * tanhf(cn);
        }
        __syncthreads();
        sh[t]       = hn[0];
        sh[t + 256] = hn[1];
        __syncthreads();
    }
}

// ------------------------------- launch -------------------------------------
extern "C" void kernel_launch(void* const* d_in, const int* in_sizes, int n_in,
                              void* d_out, int out_size)
{
    const float* x     = (const float*)d_in[0];
    const float* W_ih  = (const float*)d_in[1];
    const float* W_hh  = (const float*)d_in[2];
    const float* b_ih  = (const float*)d_in[3];
    const float* b_hh  = (const float*)d_in[4];
    const float* W_out = (const float*)d_in[5];
    const float* b_out = (const float*)d_in[6];
    float* out = (float*)d_out;

    __nv_bfloat16 *whi, *wlo, *hhi0, *hlo0, *hhi1, *hlo1;
    float *hf, *c, *G0, *br, *wihr;
    cudaGetSymbolAddress((void**)&whi,  g_whi);
    cudaGetSymbolAddress((void**)&wlo,  g_wlo);
    cudaGetSymbolAddress((void**)&hhi0, g_hhi0);
    cudaGetSymbolAddress((void**)&hlo0, g_hlo0);
    cudaGetSymbolAddress((void**)&hhi1, g_hhi1);
    cudaGetSymbolAddress((void**)&hlo1, g_hlo1);
    cudaGetSymbolAddress((void**)&hf,   g_hf);
    cudaGetSymbolAddress((void**)&c,    g_c);
    cudaGetSymbolAddress((void**)&G0,   g_G0);
    cudaGetSymbolAddress((void**)&br,   g_br);
    cudaGetSymbolAddress((void**)&wihr, g_wihr);

    cudaFuncSetAttribute(lstm_mma_step, cudaFuncAttributeMaxDynamicSharedMemorySize, SMEM_TOTAL);

    init_state<<<(BATCH * HID + 255) / 256, 256>>>((uint32_t*)hhi0, (uint32_t*)hlo0, c);
    wprep<<<(G4 * HID + 255) / 256, 256>>>(W_hh, b_ih, b_hh, W_ih, whi, wlo, br, wihr);

    dim3 grid(G4 / TNR, BATCH / TM);     // (16, 8) = 128 CTAs
    dim3 block(128);

    for (int t = 0; t < TSTEPS; ++t) {
        const __nv_bfloat16* ah = (t & 1) ? hhi1 : hhi0;
        const __nv_bfloat16* al = (t & 1) ? hlo1 : hlo0;
        __nv_bfloat16* oh = (t & 1) ? hhi0 : hhi1;
        __nv_bfloat16* ol = (t & 1) ? hlo0 : hlo1;
        float* hfp = (t == TSTEPS - 1) ? hf : nullptr;
        lstm_mma_step<<<grid, block, SMEM_TOTAL>>>(ah, al, whi, wlo, br, wihr,
                                                   x, t, c, oh, ol, hfp, nullptr);
    }
    // final hidden (hi/lo) in buf0 (T=256 even), fp32 in hf, cell in c

    lstm_mma_step<<<grid, block, SMEM_TOTAL>>>(hhi0, hlo0, whi, wlo, br, wihr,
                                               x, 0, c, hhi1, hlo1, nullptr, G0);

    decode_kernel<<<BATCH, 256>>>(hf, c, G0, W_ih, W_out, b_out, out);
}

// round 4
// speedup vs baseline: 1.9115x; 1.1053x over previous
#include <cuda_runtime.h>
#include <cuda_bf16.h>
#include <cstdint>
#include <cstddef>

// Problem constants
#define BATCH 512
#define TSTEPS 256
#define HID 512
#define G4 2048
#define DEC_STEPS 42

// MMA step config
#define TM 64                 // batch rows per CTA
#define TNR 128               // reordered gate cols per CTA (32 logical x 4 gates)
#define KC 32                 // k chunk
#define NKC (HID / KC)        // 16 chunks
#define NSTAGE 4
#define PA 40                 // smem pitch (elems): 32 + 8 pad
#define PB 40
#define ABYTES (TM * PA * 2)              // 5120
#define BBYTES (TNR * PB * 2)             // 10240
#define STAGE (2 * ABYTES + 2 * BBYTES)   // 30720 (Ahi,Alo,Bhi,Blo)
#define SMEM_TOTAL (NSTAGE * STAGE)       // 122880

// ------------------------- device scratch (no allocs) ----------------------
__device__ __align__(128) __nv_bfloat16 g_whi[G4 * HID];
__device__ __align__(128) __nv_bfloat16 g_wlo[G4 * HID];
__device__ __align__(128) __nv_bfloat16 g_hhi0[BATCH * HID];
__device__ __align__(128) __nv_bfloat16 g_hlo0[BATCH * HID];
__device__ __align__(128) __nv_bfloat16 g_hhi1[BATCH * HID];
__device__ __align__(128) __nv_bfloat16 g_hlo1[BATCH * HID];
__device__ float g_hf[BATCH * HID];
__device__ float g_c [BATCH * HID];
__device__ float g_G0[BATCH * G4];
__device__ float g_br[G4];
__device__ float g_wihr[G4];

// ------------------------------ helpers ------------------------------------
__device__ __forceinline__ uint32_t smem_u32(const void* p) {
    uint32_t a;
    asm("{ .reg .u64 t; cvta.to.shared.u64 t, %1; cvt.u32.u64 %0, t; }" : "=r"(a) : "l"(p));
    return a;
}
__device__ __forceinline__ void cpasync16(uint32_t s, const void* g) {
    asm volatile("cp.async.cg.shared.global [%0], [%1], 16;" :: "r"(s), "l"(g));
}
__device__ __forceinline__ void cpasync_commit() {
    asm volatile("cp.async.commit_group;" ::: "memory");
}
template <int N> __device__ __forceinline__ void cpasync_wait() {
    asm volatile("cp.async.wait_group %0;" :: "n"(N) : "memory");
}
__device__ __forceinline__ void ldsm_x4(uint32_t* r, uint32_t addr) {
    asm volatile("ldmatrix.sync.aligned.m8n8.x4.shared.b16 {%0,%1,%2,%3}, [%4];"
                 : "=r"(r[0]), "=r"(r[1]), "=r"(r[2]), "=r"(r[3]) : "r"(addr));
}
__device__ __forceinline__ void mma16816(float* c, const uint32_t* a, uint32_t b0, uint32_t b1) {
    asm volatile(
        "mma.sync.aligned.m16n8k16.row.col.f32.bf16.bf16.f32 "
        "{%0,%1,%2,%3}, {%4,%5,%6,%7}, {%8,%9}, {%0,%1,%2,%3};"
        : "+f"(c[0]), "+f"(c[1]), "+f"(c[2]), "+f"(c[3])
        : "r"(a[0]), "r"(a[1]), "r"(a[2]), "r"(a[3]), "r"(b0), "r"(b1));
}
__device__ __forceinline__ float sigm(float v) { return 1.0f / (1.0f + expf(-v)); }

// -------------------------- init / prep kernels -----------------------------
__global__ void init_state(uint32_t* hhi, uint32_t* hlo, float* c) {
    int i = blockIdx.x * 256 + threadIdx.x;
    if (i < BATCH * HID / 2) { hhi[i] = 0u; hlo[i] = 0u; }
    if (i < BATCH * HID) c[i] = 0.0f;
}

// Split W_hh into bf16 hi/lo with gate-interleaved row reorder:
//   old row r = q*512 + jn*32 + s  ->  new row = jn*128 + q*32 + s
__global__ void wprep(const float* __restrict__ Whh,
                      const float* __restrict__ b_ih, const float* __restrict__ b_hh,
                      const float* __restrict__ Wih,
                      __nv_bfloat16* __restrict__ whi, __nv_bfloat16* __restrict__ wlo,
                      float* __restrict__ br, float* __restrict__ wihr)
{
    int i = blockIdx.x * 256 + threadIdx.x;
    if (i >= G4 * HID) return;
    int old_r = i / HID;
    int k = i - old_r * HID;
    int q = old_r >> 9;
    int rem = old_r & 511;
    int jn = rem >> 5;
    int s = rem & 31;
    int new_r = jn * 128 + q * 32 + s;
    float w = Whh[i];
    __nv_bfloat16 hi = __float2bfloat16(w);
    whi[new_r * HID + k] = hi;
    wlo[new_r * HID + k] = __float2bfloat16(w - __bfloat162float(hi));
    if (k == 0) {
        br[new_r] = b_ih[old_r] + b_hh[old_r];
        wihr[new_r] = Wih[old_r];
    }
}

// ----------------------------- tensor LSTM step -----------------------------
// 256 threads = 8 warps in a 2(m) x 4(n) grid; warp tile 32x32.
__global__ __launch_bounds__(256, 1)
void lstm_mma_step(const __nv_bfloat16* __restrict__ ahi, const __nv_bfloat16* __restrict__ alo,
                   const __nv_bfloat16* __restrict__ whi, const __nv_bfloat16* __restrict__ wlo,
                   const float* __restrict__ br, const float* __restrict__ wihr,
                   const float* __restrict__ x, int t,
                   float* __restrict__ c,
                   __nv_bfloat16* __restrict__ hout_hi, __nv_bfloat16* __restrict__ hout_lo,
                   float* __restrict__ hf,     // non-null: also store fp32 h
                   float* __restrict__ G0)     // non-null: G0 mode (gates+bias only)
{
    extern __shared__ __align__(16) char smem[];
    const uint32_t sb = smem_u32(smem);
    const int tid = threadIdx.x;
    const int wid = tid >> 5;
    const int l = tid & 31;
    const int wm = wid >> 2;              // 0..1  (m half)
    const int wn = wid & 3;               // 0..3  (n quarter = gate)
    const int jn = blockIdx.x;            // 0..15
    const int m0 = blockIdx.y * TM;
    const int n0 = jn * TNR;              // reordered W row base

    // --------------- cp.async tile loaders ----------------------------------
    auto loadA = [&](uint32_t dst, const __nv_bfloat16* gsrc) {
        int r = tid >> 2;                 // 0..63
        int cseg = tid & 3;
        cpasync16(dst + (uint32_t)(r * (PA * 2) + cseg * 16),
                  (const char*)gsrc + (size_t)r * (HID * 2) + cseg * 16);
    };
    auto loadB = [&](uint32_t dst, const __nv_bfloat16* gsrc) {
#pragma unroll
        for (int it = 0; it < 2; ++it) {
            int slot = tid + it * 256;    // 0..511
            int r = slot >> 2;
            int cseg = slot & 3;
            cpasync16(dst + (uint32_t)(r * (PB * 2) + cseg * 16),
                      (const char*)gsrc + (size_t)r * (HID * 2) + cseg * 16);
        }
    };
    auto load_chunk = [&](int stage, int kc) {
        uint32_t st = sb + stage * STAGE;
        int k0 = kc * KC;
        loadA(st,                        ahi + (size_t)m0 * HID + k0);
        loadA(st + ABYTES,               alo + (size_t)m0 * HID + k0);
        loadB(st + 2 * ABYTES,           whi + (size_t)n0 * HID + k0);
        loadB(st + 2 * ABYTES + BBYTES,  wlo + (size_t)n0 * HID + k0);
        cpasync_commit();
    };

    // per-lane ldmatrix byte offsets
    const uint32_t aoff = (uint32_t)((l & 15) * (PA * 2) + (l >> 4) * 16);
    const uint32_t boff = (uint32_t)(((l & 7) + ((l >> 4) << 3)) * (PB * 2) + ((l >> 3) & 1) * 16);

    float acc[2][4][4];
#pragma unroll
    for (int mt = 0; mt < 2; ++mt)
#pragma unroll
        for (int nt = 0; nt < 4; ++nt)
#pragma unroll
            for (int v = 0; v < 4; ++v) acc[mt][nt][v] = 0.0f;

    // prologue: 3 chunks in flight
    load_chunk(0, 0);
    load_chunk(1, 1);
    load_chunk(2, 2);

#pragma unroll 1
    for (int kc = 0; kc < NKC; ++kc) {
        cpasync_wait<2>();                 // chunk kc resident
        __syncthreads();                   // all warps done with stage (kc-1)%4

        if (kc + 3 < NKC) load_chunk((kc + 3) & 3, kc + 3);

        const uint32_t st = sb + (kc & 3) * STAGE;
        const uint32_t stA = st + (uint32_t)(wm * 32 * (PA * 2));
        const uint32_t stB = st + 2 * ABYTES + (uint32_t)(wn * 32 * (PB * 2));
#pragma unroll
        for (int ks = 0; ks < 2; ++ks) {
            const uint32_t ka = (uint32_t)(ks * 32);   // 16 bf16 = 32B
            uint32_t ah[2][4], al[2][4];
#pragma unroll
            for (int mt = 0; mt < 2; ++mt) {
                ldsm_x4(ah[mt], stA + (uint32_t)(mt * 16 * (PA * 2)) + ka + aoff);
                ldsm_x4(al[mt], stA + ABYTES + (uint32_t)(mt * 16 * (PA * 2)) + ka + aoff);
            }
            uint32_t bh[2][4], bl[2][4];
#pragma unroll
            for (int bt = 0; bt < 2; ++bt) {
                uint32_t nb = (uint32_t)(bt * 16 * (PB * 2));
                ldsm_x4(bh[bt], stB + nb + ka + boff);
                ldsm_x4(bl[bt], stB + BBYTES + nb + ka + boff);
            }
#pragma unroll
            for (int mt = 0; mt < 2; ++mt)
#pragma unroll
                for (int nt = 0; nt < 4; ++nt) {
                    uint32_t h0 = bh[nt >> 1][(nt & 1) * 2], h1 = bh[nt >> 1][(nt & 1) * 2 + 1];
                    uint32_t l0 = bl[nt >> 1][(nt & 1) * 2], l1 = bl[nt >> 1][(nt & 1) * 2 + 1];
                    mma16816(acc[mt][nt], ah[mt], h0, h1);
                    mma16816(acc[mt][nt], ah[mt], l0, l1);
                    mma16816(acc[mt][nt], al[mt], h0, h1);
                }
        }
    }
    __syncthreads();

    // ------------------------------- epilogue --------------------------------
    // dump accumulators to smem as [64][132] fp32 (cols = q*32+s)
    float* sg = reinterpret_cast<float*>(smem);
#pragma unroll
    for (int mt = 0; mt < 2; ++mt)
#pragma unroll
        for (int nt = 0; nt < 4; ++nt) {
            int r0 = wm * 32 + mt * 16 + (l >> 2);
            int cb = wn * 32 + nt * 8 + (l & 3) * 2;
            *reinterpret_cast<float2*>(&sg[r0 * 132 + cb]) =
                make_float2(acc[mt][nt][0], acc[mt][nt][1]);
            *reinterpret_cast<float2*>(&sg[(r0 + 8) * 132 + cb]) =
                make_float2(acc[mt][nt][2], acc[mt][nt][3]);
        }
    __syncthreads();

    const int srow = tid >> 2;            // 64 rows, 4 threads/row
    const int row = m0 + srow;
    const float xv = (G0 == nullptr) ? x[row * TSTEPS + t] : 0.0f;

#pragma unroll
    for (int i = 0; i < 8; ++i) {
        int s = (tid & 3) * 8 + i;
        float d0 = sg[srow * 132 + 0 * 32 + s];
        float d1 = sg[srow * 132 + 1 * 32 + s];
        float d2 = sg[srow * 132 + 2 * 32 + s];
        float d3 = sg[srow * 132 + 3 * 32 + s];
        float b0 = br[n0 + 0 * 32 + s];
        float b1 = br[n0 + 1 * 32 + s];
        float b2 = br[n0 + 2 * 32 + s];
        float b3 = br[n0 + 3 * 32 + s];
        int col = jn * 32 + s;
        if (G0 != nullptr) {
            size_t base = (size_t)row * G4;
            G0[base + 0 * HID + col] = d0 + b0;
            G0[base + 1 * HID + col] = d1 + b1;
            G0[base + 2 * HID + col] = d2 + b2;
            G0[base + 3 * HID + col] = d3 + b3;
        } else {
            float gi = d0 + b0 + xv * wihr[n0 + 0 * 32 + s];
            float gf = d1 + b1 + xv * wihr[n0 + 1 * 32 + s];
            float gg = d2 + b2 + xv * wihr[n0 + 2 * 32 + s];
            float go = d3 + b3 + xv * wihr[n0 + 3 * 32 + s];
            int idx = row * HID + col;
            float cn = sigm(gf) * c[idx] + sigm(gi) * tanhf(gg);
            c[idx] = cn;
            float hv = sigm(go) * tanhf(cn);
            __nv_bfloat16 hi = __float2bfloat16(hv);
            hout_hi[idx] = hi;
            hout_lo[idx] = __float2bfloat16(hv - __bfloat162float(hi));
            if (hf != nullptr) hf[idx] = hv;
        }
    }
}

// ------------------------------- decoder ------------------------------------
__global__ __launch_bounds__(256)
void decode_kernel(const float* __restrict__ hidden,
                   const float* __restrict__ cell,
                   const float* __restrict__ G0,
                   const float* __restrict__ Wih,
                   const float* __restrict__ Wout,
                   const float* __restrict__ bout,
                   float* __restrict__ out)
{
    const int b = blockIdx.x;
    const int t = threadIdx.x;

    __shared__ float sh[HID];
    __shared__ float red[9];

    float g0[2][4], wv[2][4], cc[2], wo[2];
#pragma unroll
    for (int s = 0; s < 2; ++s) {
        int jj = t + s * 256;
#pragma unroll
        for (int q = 0; q < 4; ++q) {
            g0[s][q] = G0[b * G4 + q * HID + jj];
            wv[s][q] = Wih[q * HID + jj];
        }
        cc[s] = cell[b * HID + jj];
        wo[s] = Wout[jj];
        sh[jj] = hidden[b * HID + jj];
    }
    const float bo = bout[0];
    __syncthreads();

    for (int step = 0; step < DEC_STEPS; ++step) {
        float p = sh[t] * wo[0] + sh[t + 256] * wo[1];
#pragma unroll
        for (int o = 16; o > 0; o >>= 1)
            p += __shfl_down_sync(0xffffffffu, p, o);
        if ((t & 31) == 0) red[t >> 5] = p;
        __syncthreads();
        if (t < 8) {
            float v = red[t];
            v += __shfl_down_sync(0x000000ffu, v, 4);
            v += __shfl_down_sync(0x000000ffu, v, 2);
            v += __shfl_down_sync(0x000000ffu, v, 1);
            if (t == 0) red[8] = v + bo;
        }
        __syncthreads();
        const float ov = red[8];
        if (t == 0) out[b * DEC_STEPS + step] = ov;

        float hn[2];
#pragma unroll
        for (int s = 0; s < 2; ++s) {
            float gi = g0[s][0] + ov * wv[s][0];
            float gf = g0[s][1] + ov * wv[s][1];
            float gg = g0[s][2] + ov * wv[s][2];
            float go = g0[s][3] + ov * wv[s][3];
            float cn = sigm(gf) * cc[s] + sigm(gi) * tanhf(gg);
            hn[s] = sigm(go) * tanhf(cn);
        }
        __syncthreads();
        sh[t]       = hn[0];
        sh[t + 256] = hn[1];
        __syncthreads();
    }
}

// ------------------------------- launch -------------------------------------
extern "C" void kernel_launch(void* const* d_in, const int* in_sizes, int n_in,
                              void* d_out, int out_size)
{
    const float* x     = (const float*)d_in[0];
    const float* W_ih  = (const float*)d_in[1];
    const float* W_hh  = (const float*)d_in[2];
    const float* b_ih  = (const float*)d_in[3];
    const float* b_hh  = (const float*)d_in[4];
    const float* W_out = (const float*)d_in[5];
    const float* b_out = (const float*)d_in[6];
    float* out = (float*)d_out;

    __nv_bfloat16 *whi, *wlo, *hhi0, *hlo0, *hhi1, *hlo1;
    float *hf, *c, *G0, *br, *wihr;
    cudaGetSymbolAddress((void**)&whi,  g_whi);
    cudaGetSymbolAddress((void**)&wlo,  g_wlo);
    cudaGetSymbolAddress((void**)&hhi0, g_hhi0);
    cudaGetSymbolAddress((void**)&hlo0, g_hlo0);
    cudaGetSymbolAddress((void**)&hhi1, g_hhi1);
    cudaGetSymbolAddress((void**)&hlo1, g_hlo1);
    cudaGetSymbolAddress((void**)&hf,   g_hf);
    cudaGetSymbolAddress((void**)&c,    g_c);
    cudaGetSymbolAddress((void**)&G0,   g_G0);
    cudaGetSymbolAddress((void**)&br,   g_br);
    cudaGetSymbolAddress((void**)&wihr, g_wihr);

    cudaFuncSetAttribute(lstm_mma_step, cudaFuncAttributeMaxDynamicSharedMemorySize, SMEM_TOTAL);

    init_state<<<(BATCH * HID + 255) / 256, 256>>>((uint32_t*)hhi0, (uint32_t*)hlo0, c);
    wprep<<<(G4 * HID + 255) / 256, 256>>>(W_hh, b_ih, b_hh, W_ih, whi, wlo, br, wihr);

    dim3 grid(G4 / TNR, BATCH / TM);     // (16, 8) = 128 CTAs
    dim3 block(256);

    for (int t = 0; t < TSTEPS; ++t) {
        const __nv_bfloat16* ah = (t & 1) ? hhi1 : hhi0;
        const __nv_bfloat16* al = (t & 1) ? hlo1 : hlo0;
        __nv_bfloat16* oh = (t & 1) ? hhi0 : hhi1;
        __nv_bfloat16* ol = (t & 1) ? hlo0 : hlo1;
        float* hfp = (t == TSTEPS - 1) ? hf : nullptr;
        lstm_mma_step<<<grid, block, SMEM_TOTAL>>>(ah, al, whi, wlo, br, wihr,
                                                   x, t, c, oh, ol, hfp, nullptr);
    }
    // final hidden (hi/lo) in buf0 (T=256 even), fp32 in hf, cell in c

    lstm_mma_step<<<grid, block, SMEM_TOTAL>>>(hhi0, hlo0, whi, wlo, br, wihr,
                                               x, 0, c, hhi1, hlo1, nullptr, G0);

    decode_kernel<<<BATCH, 256>>>(hf, c, G0, W_ih, W_out, b_out, out);
}